// round 1
// baseline (speedup 1.0000x reference)
#include <cuda_runtime.h>
#include <cuda_bf16.h>
#include <cstdint>

// Problem constants
#define BB 2
#define TT 4096
#define CC 512
#define HH 8
#define HD 64
#define BT (BB*TT)        // 8192
#define N_QKV (3*CC)      // 1536

// Scratch (device globals; no allocation allowed)
__device__ float g_q[BB*HH*TT*HD];   // [B,H,T,HD]
__device__ float g_k[BB*HH*TT*HD];
__device__ float g_v[BB*HH*TT*HD];
__device__ float g_y[BT*CC];         // [B*T, C] attention output

// ---------------------------------------------------------------------------
// GEMM 1: QKV = x[8192,512] @ Wqkv[512,1536] + bqkv, scatter into q/k/v [B,H,T,HD]
// BM=BN=64, BK=16, 256 threads, 4x4 micro-tile per thread.
// ---------------------------------------------------------------------------
__global__ __launch_bounds__(256) void gemm_qkv_kernel(
    const float* __restrict__ x, const float* __restrict__ W,
    const float* __restrict__ bias)
{
    __shared__ float As[16][64];
    __shared__ float Bs[16][64];
    const int tid = threadIdx.x;
    const int bm = blockIdx.y * 64;
    const int bn = blockIdx.x * 64;
    const int tx = tid & 15;
    const int ty = tid >> 4;

    float acc[4][4] = {};

    for (int k0 = 0; k0 < CC; k0 += 16) {
        // Load A tile (64x16): thread loads one float4
        {
            int r = tid >> 2;            // 0..63
            int c = (tid & 3) * 4;       // 0,4,8,12
            float4 a = *(const float4*)(x + (size_t)(bm + r) * CC + k0 + c);
            As[c + 0][r] = a.x; As[c + 1][r] = a.y;
            As[c + 2][r] = a.z; As[c + 3][r] = a.w;
        }
        // Load B tile (16x64)
        {
            int rb = tid >> 4;           // 0..15
            int cb = (tid & 15) * 4;     // 0..60
            float4 b = *(const float4*)(W + (size_t)(k0 + rb) * N_QKV + bn + cb);
            *(float4*)&Bs[rb][cb] = b;
        }
        __syncthreads();
        #pragma unroll
        for (int kk = 0; kk < 16; kk++) {
            float a[4], b[4];
            #pragma unroll
            for (int i = 0; i < 4; i++) a[i] = As[kk][ty * 4 + i];
            #pragma unroll
            for (int j = 0; j < 4; j++) b[j] = Bs[kk][tx * 4 + j];
            #pragma unroll
            for (int i = 0; i < 4; i++)
                #pragma unroll
                for (int j = 0; j < 4; j++)
                    acc[i][j] += a[i] * b[j];
        }
        __syncthreads();
    }

    // Epilogue: scatter into q/k/v with [B,H,T,HD] layout
    #pragma unroll
    for (int i = 0; i < 4; i++) {
        #pragma unroll
        for (int j = 0; j < 4; j++) {
            int m = bm + ty * 4 + i;
            int n = bn + tx * 4 + j;
            float val = acc[i][j] + bias[n];
            int which = n / CC;          // 0=q,1=k,2=v
            int c = n % CC;
            int h = c >> 6;
            int d = c & 63;
            int b_ = m >> 12;            // m / 4096
            int t = m & 4095;
            float* dst = (which == 0) ? g_q : (which == 1) ? g_k : g_v;
            dst[((((size_t)b_ * HH + h) * TT) + t) * HD + d] = val;
        }
    }
}

// ---------------------------------------------------------------------------
// Flash attention: one block = 128 q-rows of one (b,h). Each thread owns one
// full q row (q[64], o[64] in regs). K/V tiles of 32 keys in smem; S tile
// staged in smem so j-loops stay rolled (small SASS, static reg indexing).
// ---------------------------------------------------------------------------
#define QROWS 128
#define KT 32

__global__ __launch_bounds__(128) void attn_kernel()
{
    __shared__ float Ks[KT][HD];
    __shared__ float Vs[KT][HD];
    __shared__ float Ss[KT][QROWS];

    const int tid = threadIdx.x;
    const int b = blockIdx.z;
    const int h = blockIdx.y;
    const int qt = (gridDim.x - 1) - blockIdx.x;   // heavy tiles first
    const int qi = qt * QROWS + tid;

    const size_t head_off = ((size_t)b * HH + h) * TT * HD;
    const float* qptr = g_q + head_off + (size_t)qi * HD;
    const float* kbase = g_k + head_off;
    const float* vbase = g_v + head_off;

    float qreg[HD];
    #pragma unroll
    for (int i = 0; i < 16; i++) {
        float4 t4 = ((const float4*)qptr)[i];
        qreg[4*i+0] = t4.x; qreg[4*i+1] = t4.y;
        qreg[4*i+2] = t4.z; qreg[4*i+3] = t4.w;
    }

    float o[HD];
    #pragma unroll
    for (int d = 0; d < HD; d++) o[d] = 0.f;
    float m = -1e30f, l = 0.f;

    const int ktiles = qt * (QROWS / KT) + (QROWS / KT); // covers causal range

    for (int kt = 0; kt < ktiles; kt++) {
        __syncthreads();
        // Load K,V tile: KT*HD = 2048 floats = 512 float4, 128 threads -> 4 each
        const float4* ksrc = (const float4*)(kbase + (size_t)kt * KT * HD);
        const float4* vsrc = (const float4*)(vbase + (size_t)kt * KT * HD);
        #pragma unroll
        for (int i = 0; i < 4; i++) {
            int f = tid + i * 128;
            ((float4*)Ks)[f] = ksrc[f];
            ((float4*)Vs)[f] = vsrc[f];
        }
        __syncthreads();

        const int jg0 = kt * KT;
        float mt = m;
        // S pass: dot + mask + running tile max; stage in smem
        #pragma unroll 1
        for (int j = 0; j < KT; j++) {
            float acc = 0.f;
            #pragma unroll
            for (int d = 0; d < HD; d++) acc += qreg[d] * Ks[j][d];
            float s = (jg0 + j <= qi) ? acc * 0.125f : -1e30f;
            Ss[j][tid] = s;
            mt = fmaxf(mt, s);
        }

        float alpha = __expf(m - mt);
        m = mt;
        l *= alpha;
        #pragma unroll
        for (int d = 0; d < HD; d++) o[d] *= alpha;

        // P pass: exp + accumulate into o
        #pragma unroll 1
        for (int j = 0; j < KT; j++) {
            float p = __expf(Ss[j][tid] - mt);
            l += p;
            #pragma unroll
            for (int d = 0; d < HD; d++) o[d] += p * Vs[j][d];
        }
    }

    const float inv = 1.f / l;
    float* yptr = g_y + ((size_t)b * TT + qi) * CC + h * HD;
    #pragma unroll
    for (int i = 0; i < 16; i++) {
        float4 t4;
        t4.x = o[4*i+0] * inv; t4.y = o[4*i+1] * inv;
        t4.z = o[4*i+2] * inv; t4.w = o[4*i+3] * inv;
        ((float4*)yptr)[i] = t4;
    }
}

// ---------------------------------------------------------------------------
// GEMM 2: out = y[8192,512] @ Wproj[512,512] + bproj
// ---------------------------------------------------------------------------
__global__ __launch_bounds__(256) void gemm_proj_kernel(
    const float* __restrict__ W, const float* __restrict__ bias,
    float* __restrict__ out)
{
    __shared__ float As[16][64];
    __shared__ float Bs[16][64];
    const int tid = threadIdx.x;
    const int bm = blockIdx.y * 64;
    const int bn = blockIdx.x * 64;
    const int tx = tid & 15;
    const int ty = tid >> 4;

    float acc[4][4] = {};

    for (int k0 = 0; k0 < CC; k0 += 16) {
        {
            int r = tid >> 2;
            int c = (tid & 3) * 4;
            float4 a = *(const float4*)(g_y + (size_t)(bm + r) * CC + k0 + c);
            As[c + 0][r] = a.x; As[c + 1][r] = a.y;
            As[c + 2][r] = a.z; As[c + 3][r] = a.w;
        }
        {
            int rb = tid >> 4;
            int cb = (tid & 15) * 4;
            float4 b = *(const float4*)(W + (size_t)(k0 + rb) * CC + bn + cb);
            *(float4*)&Bs[rb][cb] = b;
        }
        __syncthreads();
        #pragma unroll
        for (int kk = 0; kk < 16; kk++) {
            float a[4], b[4];
            #pragma unroll
            for (int i = 0; i < 4; i++) a[i] = As[kk][ty * 4 + i];
            #pragma unroll
            for (int j = 0; j < 4; j++) b[j] = Bs[kk][tx * 4 + j];
            #pragma unroll
            for (int i = 0; i < 4; i++)
                #pragma unroll
                for (int j = 0; j < 4; j++)
                    acc[i][j] += a[i] * b[j];
        }
        __syncthreads();
    }

    #pragma unroll
    for (int i = 0; i < 4; i++) {
        #pragma unroll
        for (int j = 0; j < 4; j++) {
            int m = bm + ty * 4 + i;
            int n = bn + tx * 4 + j;
            out[(size_t)m * CC + n] = acc[i][j] + bias[n];
        }
    }
}

// ---------------------------------------------------------------------------
extern "C" void kernel_launch(void* const* d_in, const int* in_sizes, int n_in,
                              void* d_out, int out_size)
{
    (void)in_sizes; (void)n_in; (void)out_size;
    const float* x     = (const float*)d_in[0];
    const float* Wqkv  = (const float*)d_in[1];
    const float* bqkv  = (const float*)d_in[2];
    const float* Wproj = (const float*)d_in[3];
    const float* bproj = (const float*)d_in[4];
    float* out = (float*)d_out;

    dim3 g1(N_QKV / 64, BT / 64);
    gemm_qkv_kernel<<<g1, 256>>>(x, Wqkv, bqkv);

    dim3 g2(TT / QROWS, HH, BB);
    attn_kernel<<<g2, 128>>>();

    dim3 g3(CC / 64, BT / 64);
    gemm_proj_kernel<<<g3, 256>>>(Wproj, bproj, out);
}

// round 4
// speedup vs baseline: 2.3393x; 2.3393x over previous
#include <cuda_runtime.h>
#include <cuda_bf16.h>
#include <cstdint>

// Problem constants
#define BB 2
#define TT 4096
#define CC 512
#define HH 8
#define HD 64
#define BT (BB*TT)        // 8192
#define N_QKV (3*CC)      // 1536

// Scratch (device globals; no allocation allowed)
__device__ float g_q[BB*HH*TT*HD];   // [B,H,T,HD]
__device__ float g_k[BB*HH*TT*HD];
__device__ float g_v[BB*HH*TT*HD];
__device__ float g_y[BT*CC];         // [B*T, C] attention output

// ---------------------------------------------------------------------------
// GEMM 1: QKV = x[8192,512] @ Wqkv[512,1536] + bqkv, scatter into q/k/v
// ---------------------------------------------------------------------------
__global__ __launch_bounds__(256) void gemm_qkv_kernel(
    const float* __restrict__ x, const float* __restrict__ W,
    const float* __restrict__ bias)
{
    __shared__ float As[16][64];
    __shared__ float Bs[16][64];
    const int tid = threadIdx.x;
    const int bm = blockIdx.y * 64;
    const int bn = blockIdx.x * 64;
    const int tx = tid & 15;
    const int ty = tid >> 4;

    float acc[4][4] = {};

    for (int k0 = 0; k0 < CC; k0 += 16) {
        {
            int r = tid >> 2;
            int c = (tid & 3) * 4;
            float4 a = *(const float4*)(x + (size_t)(bm + r) * CC + k0 + c);
            As[c + 0][r] = a.x; As[c + 1][r] = a.y;
            As[c + 2][r] = a.z; As[c + 3][r] = a.w;
        }
        {
            int rb = tid >> 4;
            int cb = (tid & 15) * 4;
            float4 b = *(const float4*)(W + (size_t)(k0 + rb) * N_QKV + bn + cb);
            *(float4*)&Bs[rb][cb] = b;
        }
        __syncthreads();
        #pragma unroll
        for (int kk = 0; kk < 16; kk++) {
            float a[4], b[4];
            #pragma unroll
            for (int i = 0; i < 4; i++) a[i] = As[kk][ty * 4 + i];
            #pragma unroll
            for (int j = 0; j < 4; j++) b[j] = Bs[kk][tx * 4 + j];
            #pragma unroll
            for (int i = 0; i < 4; i++)
                #pragma unroll
                for (int j = 0; j < 4; j++)
                    acc[i][j] += a[i] * b[j];
        }
        __syncthreads();
    }

    #pragma unroll
    for (int i = 0; i < 4; i++) {
        #pragma unroll
        for (int j = 0; j < 4; j++) {
            int m = bm + ty * 4 + i;
            int n = bn + tx * 4 + j;
            float val = acc[i][j] + bias[n];
            int which = n / CC;
            int c = n % CC;
            int h = c >> 6;
            int d = c & 63;
            int b_ = m >> 12;
            int t = m & 4095;
            float* dst = (which == 0) ? g_q : (which == 1) ? g_k : g_v;
            dst[((((size_t)b_ * HH + h) * TT) + t) * HD + d] = val;
        }
    }
}

// ---------------------------------------------------------------------------
// Flash attention with tf32 mma.sync.m16n8k8.
// Block: 128 threads (4 warps), Br=64 q-rows, Bc=64 keys per tile.
// Warp w owns q-rows [16w, 16w+16). Q frags in regs (pre-scaled by 1/8).
// K/V tiles in smem (stride 68, conflict-free frag access). P via smem.
// ---------------------------------------------------------------------------
#define QT 64
#define KTL 64
#define PADS 68

__device__ __forceinline__ uint32_t tf32c(float x) {
    uint32_t r;
    asm("cvt.rna.tf32.f32 %0, %1;" : "=r"(r) : "f"(x));
    return r;
}

__device__ __forceinline__ void mma_tf32(
    float& d0, float& d1, float& d2, float& d3,
    uint32_t a0, uint32_t a1, uint32_t a2, uint32_t a3,
    uint32_t b0, uint32_t b1)
{
    asm volatile(
        "mma.sync.aligned.m16n8k8.row.col.f32.tf32.tf32.f32 "
        "{%0,%1,%2,%3}, {%4,%5,%6,%7}, {%8,%9}, {%0,%1,%2,%3};"
        : "+f"(d0), "+f"(d1), "+f"(d2), "+f"(d3)
        : "r"(a0), "r"(a1), "r"(a2), "r"(a3), "r"(b0), "r"(b1));
}

__global__ __launch_bounds__(128) void attn_kernel()
{
    extern __shared__ float smem[];
    float* Ks = smem;                 // [64][PADS]
    float* Vs = smem + KTL * PADS;    // [64][PADS]
    float* Ps = smem + 2 * KTL * PADS;// [64][PADS]

    const int tid = threadIdx.x;
    const int w = tid >> 5;
    const int lane = tid & 31;
    const int g = lane >> 2;      // 0..7
    const int lam = lane & 3;     // 0..3

    const int b = blockIdx.z;
    const int h = blockIdx.y;
    const int qt = (gridDim.x - 1) - blockIdx.x;   // heavy tiles first
    const int q0 = qt * QT;

    const size_t head_off = ((size_t)b * HH + h) * TT * HD;
    const float* kbase = g_k + head_off;
    const float* vbase = g_v + head_off;

    const int qi0 = q0 + w * 16 + g;       // global row for c0,c1
    const int qi1 = qi0 + 8;               // global row for c2,c3

    // Load Q fragments into registers, pre-scaled by 1/sqrt(HD)=0.125 (pow2:
    // exact in tf32), converted with round-nearest.
    uint32_t qa[8][4];
    {
        const float* qr0 = g_q + head_off + (size_t)qi0 * HD;
        const float* qr1 = g_q + head_off + (size_t)qi1 * HD;
        #pragma unroll
        for (int ks = 0; ks < 8; ks++) {
            qa[ks][0] = tf32c(qr0[ks * 8 + lam] * 0.125f);
            qa[ks][1] = tf32c(qr1[ks * 8 + lam] * 0.125f);
            qa[ks][2] = tf32c(qr0[ks * 8 + lam + 4] * 0.125f);
            qa[ks][3] = tf32c(qr1[ks * 8 + lam + 4] * 0.125f);
        }
    }

    float oacc[8][4];
    #pragma unroll
    for (int n = 0; n < 8; n++)
        #pragma unroll
        for (int i = 0; i < 4; i++) oacc[n][i] = 0.f;
    float m0 = -1e30f, m1 = -1e30f, l0 = 0.f, l1 = 0.f;

    const int ktiles = qt + 1;

    for (int kt = 0; kt < ktiles; kt++) {
        __syncthreads();
        // Load K,V tile (64x64 fp32 -> tf32 in smem). 1024 float4 per array.
        {
            const float4* ksrc = (const float4*)(kbase + (size_t)kt * KTL * HD);
            const float4* vsrc = (const float4*)(vbase + (size_t)kt * KTL * HD);
            #pragma unroll
            for (int i = 0; i < 8; i++) {
                int f = tid + i * 128;          // 0..1023
                int r = f >> 4;
                int c4 = (f & 15) * 4;
                float4 kv = ksrc[f];
                float4 vv = vsrc[f];
                uint32_t* kd = (uint32_t*)&Ks[r * PADS + c4];
                uint32_t* vd = (uint32_t*)&Vs[r * PADS + c4];
                kd[0] = tf32c(kv.x); kd[1] = tf32c(kv.y);
                kd[2] = tf32c(kv.z); kd[3] = tf32c(kv.w);
                vd[0] = tf32c(vv.x); vd[1] = tf32c(vv.y);
                vd[2] = tf32c(vv.z); vd[3] = tf32c(vv.w);
            }
        }
        __syncthreads();

        // S = Q K^T (scaled). sacc[n][*] covers keys [8n, 8n+8).
        float sacc[8][4];
        #pragma unroll
        for (int n = 0; n < 8; n++)
            #pragma unroll
            for (int i = 0; i < 4; i++) sacc[n][i] = 0.f;

        #pragma unroll
        for (int ks = 0; ks < 8; ks++) {
            #pragma unroll
            for (int n = 0; n < 8; n++) {
                uint32_t b0 = __float_as_uint(Ks[(n * 8 + g) * PADS + ks * 8 + lam]);
                uint32_t b1 = __float_as_uint(Ks[(n * 8 + g) * PADS + ks * 8 + lam + 4]);
                mma_tf32(sacc[n][0], sacc[n][1], sacc[n][2], sacc[n][3],
                         qa[ks][0], qa[ks][1], qa[ks][2], qa[ks][3], b0, b1);
            }
        }

        // Causal mask (only diagonal tile needs it)
        if (kt == qt) {
            #pragma unroll
            for (int n = 0; n < 8; n++) {
                int jg = kt * KTL + n * 8 + 2 * lam;
                if (jg > qi0)     sacc[n][0] = -1e30f;
                if (jg + 1 > qi0) sacc[n][1] = -1e30f;
                if (jg > qi1)     sacc[n][2] = -1e30f;
                if (jg + 1 > qi1) sacc[n][3] = -1e30f;
            }
        }

        // Row max across tile
        float mx0 = -1e30f, mx1 = -1e30f;
        #pragma unroll
        for (int n = 0; n < 8; n++) {
            mx0 = fmaxf(mx0, fmaxf(sacc[n][0], sacc[n][1]));
            mx1 = fmaxf(mx1, fmaxf(sacc[n][2], sacc[n][3]));
        }
        mx0 = fmaxf(mx0, __shfl_xor_sync(0xffffffff, mx0, 1));
        mx0 = fmaxf(mx0, __shfl_xor_sync(0xffffffff, mx0, 2));
        mx1 = fmaxf(mx1, __shfl_xor_sync(0xffffffff, mx1, 1));
        mx1 = fmaxf(mx1, __shfl_xor_sync(0xffffffff, mx1, 2));

        float m0n = fmaxf(m0, mx0);
        float m1n = fmaxf(m1, mx1);
        float al0 = __expf(m0 - m0n);
        float al1 = __expf(m1 - m1n);
        m0 = m0n; m1 = m1n;

        #pragma unroll
        for (int n = 0; n < 8; n++) {
            oacc[n][0] *= al0; oacc[n][1] *= al0;
            oacc[n][2] *= al1; oacc[n][3] *= al1;
        }

        // P = exp(S - m), stage into per-warp smem region (tf32-rounded)
        float rs0 = 0.f, rs1 = 0.f;
        #pragma unroll
        for (int n = 0; n < 8; n++) {
            float p0 = __expf(sacc[n][0] - m0);
            float p1 = __expf(sacc[n][1] - m0);
            float p2 = __expf(sacc[n][2] - m1);
            float p3 = __expf(sacc[n][3] - m1);
            rs0 += p0 + p1;
            rs1 += p2 + p3;
            uint2* d0 = (uint2*)&Ps[(w * 16 + g) * PADS + n * 8 + 2 * lam];
            uint2* d1 = (uint2*)&Ps[(w * 16 + g + 8) * PADS + n * 8 + 2 * lam];
            *d0 = make_uint2(tf32c(p0), tf32c(p1));
            *d1 = make_uint2(tf32c(p2), tf32c(p3));
        }
        rs0 += __shfl_xor_sync(0xffffffff, rs0, 1);
        rs0 += __shfl_xor_sync(0xffffffff, rs0, 2);
        rs1 += __shfl_xor_sync(0xffffffff, rs1, 1);
        rs1 += __shfl_xor_sync(0xffffffff, rs1, 2);
        l0 = l0 * al0 + rs0;
        l1 = l1 * al1 + rs1;

        __syncwarp();

        // O += P V
        #pragma unroll
        for (int ks = 0; ks < 8; ks++) {
            uint32_t a0 = __float_as_uint(Ps[(w * 16 + g) * PADS + ks * 8 + lam]);
            uint32_t a1 = __float_as_uint(Ps[(w * 16 + g + 8) * PADS + ks * 8 + lam]);
            uint32_t a2 = __float_as_uint(Ps[(w * 16 + g) * PADS + ks * 8 + lam + 4]);
            uint32_t a3 = __float_as_uint(Ps[(w * 16 + g + 8) * PADS + ks * 8 + lam + 4]);
            #pragma unroll
            for (int n = 0; n < 8; n++) {
                uint32_t b0 = __float_as_uint(Vs[(ks * 8 + lam) * PADS + n * 8 + g]);
                uint32_t b1 = __float_as_uint(Vs[(ks * 8 + lam + 4) * PADS + n * 8 + g]);
                mma_tf32(oacc[n][0], oacc[n][1], oacc[n][2], oacc[n][3],
                         a0, a1, a2, a3, b0, b1);
            }
        }
        __syncwarp();
    }

    // Write O / l to g_y [B*T, C] at head column offset
    const float inv0 = 1.f / l0;
    const float inv1 = 1.f / l1;
    float* y0 = g_y + ((size_t)b * TT + qi0) * CC + h * HD;
    float* y1 = g_y + ((size_t)b * TT + qi1) * CC + h * HD;
    #pragma unroll
    for (int n = 0; n < 8; n++) {
        int c = n * 8 + 2 * lam;
        *(float2*)&y0[c] = make_float2(oacc[n][0] * inv0, oacc[n][1] * inv0);
        *(float2*)&y1[c] = make_float2(oacc[n][2] * inv1, oacc[n][3] * inv1);
    }
}

// ---------------------------------------------------------------------------
// GEMM 2: out = y[8192,512] @ Wproj[512,512] + bproj
// ---------------------------------------------------------------------------
__global__ __launch_bounds__(256) void gemm_proj_kernel(
    const float* __restrict__ W, const float* __restrict__ bias,
    float* __restrict__ out)
{
    __shared__ float As[16][64];
    __shared__ float Bs[16][64];
    const int tid = threadIdx.x;
    const int bm = blockIdx.y * 64;
    const int bn = blockIdx.x * 64;
    const int tx = tid & 15;
    const int ty = tid >> 4;

    float acc[4][4] = {};

    for (int k0 = 0; k0 < CC; k0 += 16) {
        {
            int r = tid >> 2;
            int c = (tid & 3) * 4;
            float4 a = *(const float4*)(g_y + (size_t)(bm + r) * CC + k0 + c);
            As[c + 0][r] = a.x; As[c + 1][r] = a.y;
            As[c + 2][r] = a.z; As[c + 3][r] = a.w;
        }
        {
            int rb = tid >> 4;
            int cb = (tid & 15) * 4;
            float4 b = *(const float4*)(W + (size_t)(k0 + rb) * CC + bn + cb);
            *(float4*)&Bs[rb][cb] = b;
        }
        __syncthreads();
        #pragma unroll
        for (int kk = 0; kk < 16; kk++) {
            float a[4], b[4];
            #pragma unroll
            for (int i = 0; i < 4; i++) a[i] = As[kk][ty * 4 + i];
            #pragma unroll
            for (int j = 0; j < 4; j++) b[j] = Bs[kk][tx * 4 + j];
            #pragma unroll
            for (int i = 0; i < 4; i++)
                #pragma unroll
                for (int j = 0; j < 4; j++)
                    acc[i][j] += a[i] * b[j];
        }
        __syncthreads();
    }

    #pragma unroll
    for (int i = 0; i < 4; i++) {
        #pragma unroll
        for (int j = 0; j < 4; j++) {
            int m = bm + ty * 4 + i;
            int n = bn + tx * 4 + j;
            out[(size_t)m * CC + n] = acc[i][j] + bias[n];
        }
    }
}

// ---------------------------------------------------------------------------
extern "C" void kernel_launch(void* const* d_in, const int* in_sizes, int n_in,
                              void* d_out, int out_size)
{
    (void)in_sizes; (void)n_in; (void)out_size;
    const float* x     = (const float*)d_in[0];
    const float* Wqkv  = (const float*)d_in[1];
    const float* bqkv  = (const float*)d_in[2];
    const float* Wproj = (const float*)d_in[3];
    const float* bproj = (const float*)d_in[4];
    float* out = (float*)d_out;

    static int smem_set = 0;
    const int attn_smem = 3 * KTL * PADS * (int)sizeof(float);  // 52224
    if (!smem_set) {
        cudaFuncSetAttribute(attn_kernel,
                             cudaFuncAttributeMaxDynamicSharedMemorySize,
                             attn_smem);
        smem_set = 1;
    }

    dim3 g1(N_QKV / 64, BT / 64);
    gemm_qkv_kernel<<<g1, 256>>>(x, Wqkv, bqkv);

    dim3 g2(TT / QT, HH, BB);
    attn_kernel<<<g2, 128, attn_smem>>>();

    dim3 g3(CC / 64, BT / 64);
    gemm_proj_kernel<<<g3, 256>>>(Wproj, bproj, out);
}

// round 7
// speedup vs baseline: 3.0675x; 1.3113x over previous
#include <cuda_runtime.h>
#include <cuda_bf16.h>
#include <cstdint>

// Problem constants
#define BB 2
#define TT 4096
#define CC 512
#define HH 8
#define HD 64
#define BT (BB*TT)        // 8192
#define N_QKV (3*CC)      // 1536

// Scratch (device globals; no allocation allowed)
__device__ float g_q[BB*HH*TT*HD];   // [B,H,T,HD]
__device__ float g_k[BB*HH*TT*HD];
__device__ float g_v[BB*HH*TT*HD];
__device__ float g_y[BT*CC];         // [B*T, C] attention output

__device__ __forceinline__ uint32_t tf32c(float x) {
    uint32_t r;
    asm("cvt.rna.tf32.f32 %0, %1;" : "=r"(r) : "f"(x));
    return r;
}

__device__ __forceinline__ void mma_tf32(
    float& d0, float& d1, float& d2, float& d3,
    uint32_t a0, uint32_t a1, uint32_t a2, uint32_t a3,
    uint32_t b0, uint32_t b1)
{
    asm volatile(
        "mma.sync.aligned.m16n8k8.row.col.f32.tf32.tf32.f32 "
        "{%0,%1,%2,%3}, {%4,%5,%6,%7}, {%8,%9}, {%0,%1,%2,%3};"
        : "+f"(d0), "+f"(d1), "+f"(d2), "+f"(d3)
        : "r"(a0), "r"(a1), "r"(a2), "r"(a3), "r"(b0), "r"(b1));
}

// ---------------------------------------------------------------------------
// tf32 GEMM: out[M=8192, NN] = A[8192,512] @ W[512,NN] + bias.
// Block 128 thr (4 warps), tile BM=64 x BN=64, BK=64 staged in smem (tf32).
// Warp w owns rows [16w,16w+16) x all 64 cols: 8 n-mmas per k8-step.
// SCATTER=true: qkv epilogue scattering into g_q/g_k/g_v [B,H,T,HD].
// A_IS_Y=true: read A from device-global g_y (symbol must bind in device
// code — passing g_y from host passes the host shadow address! R5 bug).
// ---------------------------------------------------------------------------
#define GPAD 68

template<int NN, bool SCATTER, bool A_IS_Y>
__global__ __launch_bounds__(128) void gemm_tf32_kernel(
    const float* __restrict__ A_arg, const float* __restrict__ W,
    const float* __restrict__ bias, float* __restrict__ out)
{
    __shared__ float As[64 * GPAD];
    __shared__ float Bs[64 * GPAD];

    const float* __restrict__ A = A_IS_Y ? (const float*)g_y : A_arg;

    const int tid = threadIdx.x;
    const int w = tid >> 5;
    const int lane = tid & 31;
    const int g = lane >> 2;
    const int lam = lane & 3;

    const int bn = blockIdx.x * 64;
    const int bm = blockIdx.y * 64;

    float sacc[8][4];
    #pragma unroll
    for (int n = 0; n < 8; n++)
        #pragma unroll
        for (int i = 0; i < 4; i++) sacc[n][i] = 0.f;

    for (int k0 = 0; k0 < CC; k0 += 64) {
        __syncthreads();
        // Stage A tile (64 rows x 64 k) and B tile (64 k x 64 n) as tf32
        #pragma unroll
        for (int i = 0; i < 8; i++) {
            int f = tid + i * 128;           // 0..1023
            int r = f >> 4;
            int c4 = (f & 15) * 4;
            float4 av = *(const float4*)(A + (size_t)(bm + r) * CC + k0 + c4);
            float4 bv = *(const float4*)(W + (size_t)(k0 + r) * NN + bn + c4);
            uint32_t* ad = (uint32_t*)&As[r * GPAD + c4];
            uint32_t* bd = (uint32_t*)&Bs[r * GPAD + c4];
            ad[0] = tf32c(av.x); ad[1] = tf32c(av.y);
            ad[2] = tf32c(av.z); ad[3] = tf32c(av.w);
            bd[0] = tf32c(bv.x); bd[1] = tf32c(bv.y);
            bd[2] = tf32c(bv.z); bd[3] = tf32c(bv.w);
        }
        __syncthreads();

        #pragma unroll
        for (int ks = 0; ks < 8; ks++) {
            uint32_t a0 = __float_as_uint(As[(w * 16 + g) * GPAD + ks * 8 + lam]);
            uint32_t a1 = __float_as_uint(As[(w * 16 + g + 8) * GPAD + ks * 8 + lam]);
            uint32_t a2 = __float_as_uint(As[(w * 16 + g) * GPAD + ks * 8 + lam + 4]);
            uint32_t a3 = __float_as_uint(As[(w * 16 + g + 8) * GPAD + ks * 8 + lam + 4]);
            #pragma unroll
            for (int n = 0; n < 8; n++) {
                uint32_t b0 = __float_as_uint(Bs[(ks * 8 + lam) * GPAD + n * 8 + g]);
                uint32_t b1 = __float_as_uint(Bs[(ks * 8 + lam + 4) * GPAD + n * 8 + g]);
                mma_tf32(sacc[n][0], sacc[n][1], sacc[n][2], sacc[n][3],
                         a0, a1, a2, a3, b0, b1);
            }
        }
    }

    // Epilogue
    const int m0 = bm + w * 16 + g;
    const int m1 = m0 + 8;
    #pragma unroll
    for (int n = 0; n < 8; n++) {
        #pragma unroll
        for (int p = 0; p < 2; p++) {
            int col = bn + n * 8 + 2 * lam + p;
            float bsv = bias[col];
            float v0 = sacc[n][0 + p] + bsv;
            float v1 = sacc[n][2 + p] + bsv;
            if (SCATTER) {
                int which = col / CC;
                int c = col % CC;
                int h = c >> 6;
                int d = c & 63;
                float* dst = (which == 0) ? g_q : (which == 1) ? g_k : g_v;
                size_t base = (((size_t)(m0 >> 12) * HH + h) * TT) * HD + d;
                dst[base + (size_t)(m0 & 4095) * HD] = v0;
                dst[base + (size_t)(m1 & 4095) * HD] = v1;
            } else {
                out[(size_t)m0 * NN + col] = v0;
                out[(size_t)m1 * NN + col] = v1;
            }
        }
    }
}

// ---------------------------------------------------------------------------
// Flash attention with tf32 mma.sync.m16n8k8 (unchanged from R4).
// ---------------------------------------------------------------------------
#define QT 64
#define KTL 64
#define PADS 68

__global__ __launch_bounds__(128) void attn_kernel()
{
    extern __shared__ float smem[];
    float* Ks = smem;                 // [64][PADS]
    float* Vs = smem + KTL * PADS;    // [64][PADS]
    float* Ps = smem + 2 * KTL * PADS;// [64][PADS]

    const int tid = threadIdx.x;
    const int w = tid >> 5;
    const int lane = tid & 31;
    const int g = lane >> 2;
    const int lam = lane & 3;

    const int b = blockIdx.z;
    const int h = blockIdx.y;
    const int qt = (gridDim.x - 1) - blockIdx.x;   // heavy tiles first
    const int q0 = qt * QT;

    const size_t head_off = ((size_t)b * HH + h) * TT * HD;
    const float* kbase = g_k + head_off;
    const float* vbase = g_v + head_off;

    const int qi0 = q0 + w * 16 + g;
    const int qi1 = qi0 + 8;

    uint32_t qa[8][4];
    {
        const float* qr0 = g_q + head_off + (size_t)qi0 * HD;
        const float* qr1 = g_q + head_off + (size_t)qi1 * HD;
        #pragma unroll
        for (int ks = 0; ks < 8; ks++) {
            qa[ks][0] = tf32c(qr0[ks * 8 + lam] * 0.125f);
            qa[ks][1] = tf32c(qr1[ks * 8 + lam] * 0.125f);
            qa[ks][2] = tf32c(qr0[ks * 8 + lam + 4] * 0.125f);
            qa[ks][3] = tf32c(qr1[ks * 8 + lam + 4] * 0.125f);
        }
    }

    float oacc[8][4];
    #pragma unroll
    for (int n = 0; n < 8; n++)
        #pragma unroll
        for (int i = 0; i < 4; i++) oacc[n][i] = 0.f;
    float m0 = -1e30f, m1 = -1e30f, l0 = 0.f, l1 = 0.f;

    const int ktiles = qt + 1;

    for (int kt = 0; kt < ktiles; kt++) {
        __syncthreads();
        {
            const float4* ksrc = (const float4*)(kbase + (size_t)kt * KTL * HD);
            const float4* vsrc = (const float4*)(vbase + (size_t)kt * KTL * HD);
            #pragma unroll
            for (int i = 0; i < 8; i++) {
                int f = tid + i * 128;
                int r = f >> 4;
                int c4 = (f & 15) * 4;
                float4 kv = ksrc[f];
                float4 vv = vsrc[f];
                uint32_t* kd = (uint32_t*)&Ks[r * PADS + c4];
                uint32_t* vd = (uint32_t*)&Vs[r * PADS + c4];
                kd[0] = tf32c(kv.x); kd[1] = tf32c(kv.y);
                kd[2] = tf32c(kv.z); kd[3] = tf32c(kv.w);
                vd[0] = tf32c(vv.x); vd[1] = tf32c(vv.y);
                vd[2] = tf32c(vv.z); vd[3] = tf32c(vv.w);
            }
        }
        __syncthreads();

        float sacc[8][4];
        #pragma unroll
        for (int n = 0; n < 8; n++)
            #pragma unroll
            for (int i = 0; i < 4; i++) sacc[n][i] = 0.f;

        #pragma unroll
        for (int ks = 0; ks < 8; ks++) {
            #pragma unroll
            for (int n = 0; n < 8; n++) {
                uint32_t b0 = __float_as_uint(Ks[(n * 8 + g) * PADS + ks * 8 + lam]);
                uint32_t b1 = __float_as_uint(Ks[(n * 8 + g) * PADS + ks * 8 + lam + 4]);
                mma_tf32(sacc[n][0], sacc[n][1], sacc[n][2], sacc[n][3],
                         qa[ks][0], qa[ks][1], qa[ks][2], qa[ks][3], b0, b1);
            }
        }

        if (kt == qt) {
            #pragma unroll
            for (int n = 0; n < 8; n++) {
                int jg = kt * KTL + n * 8 + 2 * lam;
                if (jg > qi0)     sacc[n][0] = -1e30f;
                if (jg + 1 > qi0) sacc[n][1] = -1e30f;
                if (jg > qi1)     sacc[n][2] = -1e30f;
                if (jg + 1 > qi1) sacc[n][3] = -1e30f;
            }
        }

        float mx0 = -1e30f, mx1 = -1e30f;
        #pragma unroll
        for (int n = 0; n < 8; n++) {
            mx0 = fmaxf(mx0, fmaxf(sacc[n][0], sacc[n][1]));
            mx1 = fmaxf(mx1, fmaxf(sacc[n][2], sacc[n][3]));
        }
        mx0 = fmaxf(mx0, __shfl_xor_sync(0xffffffff, mx0, 1));
        mx0 = fmaxf(mx0, __shfl_xor_sync(0xffffffff, mx0, 2));
        mx1 = fmaxf(mx1, __shfl_xor_sync(0xffffffff, mx1, 1));
        mx1 = fmaxf(mx1, __shfl_xor_sync(0xffffffff, mx1, 2));

        float m0n = fmaxf(m0, mx0);
        float m1n = fmaxf(m1, mx1);
        float al0 = __expf(m0 - m0n);
        float al1 = __expf(m1 - m1n);
        m0 = m0n; m1 = m1n;

        #pragma unroll
        for (int n = 0; n < 8; n++) {
            oacc[n][0] *= al0; oacc[n][1] *= al0;
            oacc[n][2] *= al1; oacc[n][3] *= al1;
        }

        float rs0 = 0.f, rs1 = 0.f;
        #pragma unroll
        for (int n = 0; n < 8; n++) {
            float p0 = __expf(sacc[n][0] - m0);
            float p1 = __expf(sacc[n][1] - m0);
            float p2 = __expf(sacc[n][2] - m1);
            float p3 = __expf(sacc[n][3] - m1);
            rs0 += p0 + p1;
            rs1 += p2 + p3;
            uint2* d0 = (uint2*)&Ps[(w * 16 + g) * PADS + n * 8 + 2 * lam];
            uint2* d1 = (uint2*)&Ps[(w * 16 + g + 8) * PADS + n * 8 + 2 * lam];
            *d0 = make_uint2(tf32c(p0), tf32c(p1));
            *d1 = make_uint2(tf32c(p2), tf32c(p3));
        }
        rs0 += __shfl_xor_sync(0xffffffff, rs0, 1);
        rs0 += __shfl_xor_sync(0xffffffff, rs0, 2);
        rs1 += __shfl_xor_sync(0xffffffff, rs1, 1);
        rs1 += __shfl_xor_sync(0xffffffff, rs1, 2);
        l0 = l0 * al0 + rs0;
        l1 = l1 * al1 + rs1;

        __syncwarp();

        #pragma unroll
        for (int ks = 0; ks < 8; ks++) {
            uint32_t a0 = __float_as_uint(Ps[(w * 16 + g) * PADS + ks * 8 + lam]);
            uint32_t a1 = __float_as_uint(Ps[(w * 16 + g + 8) * PADS + ks * 8 + lam]);
            uint32_t a2 = __float_as_uint(Ps[(w * 16 + g) * PADS + ks * 8 + lam + 4]);
            uint32_t a3 = __float_as_uint(Ps[(w * 16 + g + 8) * PADS + ks * 8 + lam + 4]);
            #pragma unroll
            for (int n = 0; n < 8; n++) {
                uint32_t b0 = __float_as_uint(Vs[(ks * 8 + lam) * PADS + n * 8 + g]);
                uint32_t b1 = __float_as_uint(Vs[(ks * 8 + lam + 4) * PADS + n * 8 + g]);
                mma_tf32(oacc[n][0], oacc[n][1], oacc[n][2], oacc[n][3],
                         a0, a1, a2, a3, b0, b1);
            }
        }
        __syncwarp();
    }

    const float inv0 = 1.f / l0;
    const float inv1 = 1.f / l1;
    float* y0 = g_y + ((size_t)b * TT + qi0) * CC + h * HD;
    float* y1 = g_y + ((size_t)b * TT + qi1) * CC + h * HD;
    #pragma unroll
    for (int n = 0; n < 8; n++) {
        int c = n * 8 + 2 * lam;
        *(float2*)&y0[c] = make_float2(oacc[n][0] * inv0, oacc[n][1] * inv0);
        *(float2*)&y1[c] = make_float2(oacc[n][2] * inv1, oacc[n][3] * inv1);
    }
}

// ---------------------------------------------------------------------------
extern "C" void kernel_launch(void* const* d_in, const int* in_sizes, int n_in,
                              void* d_out, int out_size)
{
    (void)in_sizes; (void)n_in; (void)out_size;
    const float* x     = (const float*)d_in[0];
    const float* Wqkv  = (const float*)d_in[1];
    const float* bqkv  = (const float*)d_in[2];
    const float* Wproj = (const float*)d_in[3];
    const float* bproj = (const float*)d_in[4];
    float* out = (float*)d_out;

    static int smem_set = 0;
    const int attn_smem = 3 * KTL * PADS * (int)sizeof(float);  // 52224
    if (!smem_set) {
        cudaFuncSetAttribute(attn_kernel,
                             cudaFuncAttributeMaxDynamicSharedMemorySize,
                             attn_smem);
        smem_set = 1;
    }

    dim3 g1(N_QKV / 64, BT / 64);
    gemm_tf32_kernel<N_QKV, true, false><<<g1, 128>>>(x, Wqkv, bqkv, nullptr);

    dim3 g2(TT / QT, HH, BB);
    attn_kernel<<<g2, 128, attn_smem>>>();

    dim3 g3(CC / 64, BT / 64);
    gemm_tf32_kernel<CC, false, true><<<g3, 128>>>(nullptr, Wproj, bproj, out);
}